// round 5
// baseline (speedup 1.0000x reference)
#include <cuda_runtime.h>
#include <cuda_fp16.h>
#include <stdint.h>
#include <math.h>

#define D_MODEL 1024
#define T_SEQ   2048
#define BATCH   2
#define NROWS   (BATCH * T_SEQ)
#define DFF     4096
#define NHEADS  16
#define HDIM    64

// ---------------- scratch ----------------
__device__ __align__(16) float g_h   [NROWS * D_MODEL];
__device__ __align__(16) float g_qkv [NROWS * 3 * D_MODEL];   // only Q cols used now
__device__ __align__(16) float g_attn[NROWS * D_MODEL];
__device__ __align__(16) float g_x1  [NROWS * D_MODEL];
__device__ __align__(16) float g_h2  [NROWS * D_MODEL];
__device__ __align__(16) float g_ff  [NROWS * DFF];
// fp16 K [bh][t][d], fp16 V^T [bh][d][t]
__device__ __align__(16) __half g_k16 [BATCH * NHEADS * T_SEQ * HDIM];
__device__ __align__(16) __half g_v16t[BATCH * NHEADS * HDIM * T_SEQ];
// rna-tf32 rounded weights
#define SZ_QKV  (D_MODEL * 3 * D_MODEL)
#define SZ_PROJ (D_MODEL * D_MODEL)
#define SZ_MLP1 (D_MODEL * DFF)
#define SZ_MLP2 (DFF * D_MODEL)
#define W_QKV  0
#define W_PROJ (W_QKV + SZ_QKV)
#define W_MLP1 (W_PROJ + SZ_PROJ)
#define W_MLP2 (W_MLP1 + SZ_MLP1)
#define W_TOT  (W_MLP2 + SZ_MLP2)
__device__ __align__(16) float g_w[W_TOT];

// ---------------- helpers ----------------
__device__ __forceinline__ float to_tf32(float f) {
    uint32_t u;
    asm("cvt.rna.tf32.f32 %0, %1;" : "=r"(u) : "f"(f));
    return __uint_as_float(u);
}

__device__ __forceinline__ void mma_tf32(float* d,
                                         float a0, float a1, float a2, float a3,
                                         float b0, float b1) {
    asm volatile(
        "mma.sync.aligned.m16n8k8.row.col.f32.tf32.tf32.f32 "
        "{%0,%1,%2,%3}, {%4,%5,%6,%7}, {%8,%9}, {%0,%1,%2,%3};\n"
        : "+f"(d[0]), "+f"(d[1]), "+f"(d[2]), "+f"(d[3])
        : "r"(__float_as_uint(a0)), "r"(__float_as_uint(a1)),
          "r"(__float_as_uint(a2)), "r"(__float_as_uint(a3)),
          "r"(__float_as_uint(b0)), "r"(__float_as_uint(b1)));
}

__device__ __forceinline__ void mma_f16(float* d,
                                        uint32_t a0, uint32_t a1, uint32_t a2, uint32_t a3,
                                        uint32_t b0, uint32_t b1) {
    asm volatile(
        "mma.sync.aligned.m16n8k16.row.col.f32.f16.f16.f32 "
        "{%0,%1,%2,%3}, {%4,%5,%6,%7}, {%8,%9}, {%0,%1,%2,%3};\n"
        : "+f"(d[0]), "+f"(d[1]), "+f"(d[2]), "+f"(d[3])
        : "r"(a0), "r"(a1), "r"(a2), "r"(a3), "r"(b0), "r"(b1));
}

__device__ __forceinline__ uint32_t packh2(float lo, float hi) {
    __half2 h = __floats2half2_rn(lo, hi);
    return *reinterpret_cast<uint32_t*>(&h);
}

__device__ __forceinline__ void cp16(uint32_t s, const void* g) {
    asm volatile("cp.async.cg.shared.global [%0], [%1], 16;\n" :: "r"(s), "l"(g));
}
__device__ __forceinline__ void cp_commit() { asm volatile("cp.async.commit_group;\n"); }
__device__ __forceinline__ void cp_wait1()  { asm volatile("cp.async.wait_group 1;\n"); }
__device__ __forceinline__ void cp_wait0()  { asm volatile("cp.async.wait_group 0;\n"); }

// ---------------- weight rna-tf32 conversion ----------------
__global__ void cvt_kernel(const float* __restrict__ src, float* __restrict__ dst, int n4) {
    const int i = blockIdx.x * blockDim.x + threadIdx.x;
    if (i < n4) {
        float4 v = reinterpret_cast<const float4*>(src)[i];
        v.x = to_tf32(v.x); v.y = to_tf32(v.y);
        v.z = to_tf32(v.z); v.w = to_tf32(v.w);
        reinterpret_cast<float4*>(dst)[i] = v;
    }
}

// ---------------- layernorm (rna-rounded output) ----------------
__global__ void ln_kernel(const float* __restrict__ x,
                          const float* __restrict__ g,
                          const float* __restrict__ b,
                          float* __restrict__ out) {
    const int row = blockIdx.x;
    const int tid = threadIdx.x;
    const float4 v = reinterpret_cast<const float4*>(x + (size_t)row * D_MODEL)[tid];
    float s  = v.x + v.y + v.z + v.w;
    float sq = v.x*v.x + v.y*v.y + v.z*v.z + v.w*v.w;

    __shared__ float rs[256];
    __shared__ float rq[256];
    rs[tid] = s; rq[tid] = sq;
    __syncthreads();
    #pragma unroll
    for (int st = 128; st > 0; st >>= 1) {
        if (tid < st) { rs[tid] += rs[tid + st]; rq[tid] += rq[tid + st]; }
        __syncthreads();
    }
    const float mean = rs[0] * (1.0f / D_MODEL);
    const float var  = rq[0] * (1.0f / D_MODEL) - mean * mean;
    const float rstd = rsqrtf(var + 1e-5f);

    const float4 gv = reinterpret_cast<const float4*>(g)[tid];
    const float4 bv = reinterpret_cast<const float4*>(b)[tid];
    float4 o;
    o.x = to_tf32((v.x - mean) * rstd * gv.x + bv.x);
    o.y = to_tf32((v.y - mean) * rstd * gv.y + bv.y);
    o.z = to_tf32((v.z - mean) * rstd * gv.z + bv.z);
    o.w = to_tf32((v.w - mean) * rstd * gv.w + bv.w);
    reinterpret_cast<float4*>(out + (size_t)row * D_MODEL)[tid] = o;
}

// ---------------- tf32 GEMM, cp.async double-buffered ----------------
// EPI 0: qkv — Q cols -> fp32 tf32-rounded; K cols -> fp16 [bh][t][d]; V cols -> fp16^T [bh][d][t]
// EPI 1: bias + exact GELU, rounded
// EPI 2: bias + residual (fp32)
#define BM 128
#define BN 128
#define BK 32
#define AS_STRIDE 36
#define BS_STRIDE 136
#define A_TILE (BM * AS_STRIDE)
#define B_TILE (BK * BS_STRIDE)
#define GEMM_SMEM ((A_TILE + B_TILE) * 2 * 4)

template<int EPI>
__global__ void __launch_bounds__(256, 2)
gemm_tf32_kernel(const float* __restrict__ A, const float* __restrict__ B,
                 const float* __restrict__ bias, const float* __restrict__ res,
                 float* __restrict__ C, __half* __restrict__ k16,
                 __half* __restrict__ v16t, int M, int N, int K) {
    extern __shared__ float sm[];
    const uint32_t smem_u32 = (uint32_t)__cvta_generic_to_shared(sm);

    const int tid    = threadIdx.x;
    const int lane   = tid & 31;
    const int warp   = tid >> 5;
    const int warp_m = warp >> 1;
    const int warp_n = warp & 1;
    const int bm = blockIdx.y * BM;
    const int bn = blockIdx.x * BN;
    const int lg = lane >> 2;
    const int lt = lane & 3;

    float c[2][8][4];
    #pragma unroll
    for (int i = 0; i < 2; i++)
        #pragma unroll
        for (int j = 0; j < 8; j++)
            #pragma unroll
            for (int k = 0; k < 4; k++) c[i][j][k] = 0.0f;

    const int a_row = tid >> 3;
    const int a_col = (tid & 7) * 4;
    const int b_row = tid >> 5;
    const int b_col = (tid & 31) * 4;
    const int KT = K / BK;

    auto load_tile = [&](int k0, int st) {
        const uint32_t abase = smem_u32 + st * A_TILE * 4;
        const uint32_t bbase = smem_u32 + (2 * A_TILE + st * B_TILE) * 4;
        #pragma unroll
        for (int i = 0; i < 4; i++) {
            const int row = a_row + i * 32;
            cp16(abase + (row * AS_STRIDE + a_col) * 4,
                 &A[(size_t)(bm + row) * K + k0 + a_col]);
        }
        #pragma unroll
        for (int i = 0; i < 4; i++) {
            const int row = b_row + i * 8;
            cp16(bbase + (row * BS_STRIDE + b_col) * 4,
                 &B[(size_t)(k0 + row) * N + bn + b_col]);
        }
        cp_commit();
    };

    load_tile(0, 0);

    for (int kt = 0; kt < KT; kt++) {
        const int st = kt & 1;
        if (kt + 1 < KT) { load_tile((kt + 1) * BK, st ^ 1); cp_wait1(); }
        else             { cp_wait0(); }
        __syncthreads();

        const float* As = sm + st * A_TILE;
        const float* Bs = sm + 2 * A_TILE + st * B_TILE;

        #pragma unroll
        for (int ks = 0; ks < 4; ks++) {
            float af[2][4];
            #pragma unroll
            for (int mi = 0; mi < 2; mi++) {
                const int m = warp_m * 32 + mi * 16 + lg;
                const int k = ks * 8 + lt;
                af[mi][0] = As[m * AS_STRIDE + k];
                af[mi][1] = As[(m + 8) * AS_STRIDE + k];
                af[mi][2] = As[m * AS_STRIDE + k + 4];
                af[mi][3] = As[(m + 8) * AS_STRIDE + k + 4];
            }
            float bf[8][2];
            #pragma unroll
            for (int nt = 0; nt < 8; nt++) {
                const int n = warp_n * 64 + nt * 8 + lg;
                const int k = ks * 8 + lt;
                bf[nt][0] = Bs[k * BS_STRIDE + n];
                bf[nt][1] = Bs[(k + 4) * BS_STRIDE + n];
            }
            #pragma unroll
            for (int mi = 0; mi < 2; mi++)
                #pragma unroll
                for (int nt = 0; nt < 8; nt++)
                    mma_tf32(c[mi][nt], af[mi][0], af[mi][1], af[mi][2], af[mi][3],
                             bf[nt][0], bf[nt][1]);
        }
        __syncthreads();
    }

    #pragma unroll
    for (int mi = 0; mi < 2; mi++) {
        #pragma unroll
        for (int nt = 0; nt < 8; nt++) {
            const int col = bn + warp_n * 64 + nt * 8 + 2 * lt;
            const float b0 = bias[col], b1 = bias[col + 1];
            #pragma unroll
            for (int half = 0; half < 2; half++) {
                const int row = bm + warp_m * 32 + mi * 16 + lg + half * 8;
                float v0 = c[mi][nt][half * 2 + 0] + b0;
                float v1 = c[mi][nt][half * 2 + 1] + b1;
                if (EPI == 0) {
                    if (col < D_MODEL) {
                        // Q: fp32 rounded
                        float2 o; o.x = to_tf32(v0); o.y = to_tf32(v1);
                        *reinterpret_cast<float2*>(&C[(size_t)row * N + col]) = o;
                    } else {
                        const int bb = row >> 11;          // batch
                        const int t  = row & (T_SEQ - 1);  // token
                        if (col < 2 * D_MODEL) {
                            // K: fp16 [bh][t][d]
                            const int hh = (col - D_MODEL) >> 6;
                            const int d  = (col - D_MODEL) & 63;
                            const size_t idx =
                                (((size_t)(bb * NHEADS + hh) * T_SEQ) + t) * HDIM + d;
                            __half2 hv = __floats2half2_rn(v0, v1);
                            *reinterpret_cast<__half2*>(&k16[idx]) = hv;
                        } else {
                            // V: fp16 transposed [bh][d][t]
                            const int hh = (col - 2 * D_MODEL) >> 6;
                            const int d  = (col - 2 * D_MODEL) & 63;
                            const size_t base = (size_t)(bb * NHEADS + hh) * HDIM;
                            v16t[(base + d)     * T_SEQ + t] = __float2half_rn(v0);
                            v16t[(base + d + 1) * T_SEQ + t] = __float2half_rn(v1);
                        }
                    }
                } else {
                    if (EPI == 1) {
                        v0 = 0.5f * v0 * (1.0f + erff(v0 * 0.70710678118654752f));
                        v1 = 0.5f * v1 * (1.0f + erff(v1 * 0.70710678118654752f));
                        v0 = to_tf32(v0); v1 = to_tf32(v1);
                    } else {
                        v0 += res[(size_t)row * N + col];
                        v1 += res[(size_t)row * N + col + 1];
                    }
                    float2 o; o.x = v0; o.y = v1;
                    *reinterpret_cast<float2*>(&C[(size_t)row * N + col]) = o;
                }
            }
        }
    }
}

// ---------------- causal flash attention v4: fp16 m16n8k16 ----------------
// smem (halves): Q [128][QH] | K0,K1 [64][KH] | VT0,VT1 [64][VTH]
#define QH  72
#define KH  72
#define VTH 72
#define Q_OFF   0
#define Q_HALF  (128 * QH)             // 9216
#define K_OFF   Q_HALF
#define K_HALF  (64 * KH)              // 4608
#define VT_OFF  (K_OFF + 2 * K_HALF)   // 18432
#define VT_HALF (64 * VTH)
#define ATT_SMEM ((VT_OFF + 2 * VT_HALF) * 2)  // 55296 bytes

__global__ void __launch_bounds__(256, 2)
attn_kernel(const float* __restrict__ qkv, const __half* __restrict__ k16,
            const __half* __restrict__ v16t, float* __restrict__ out) {
    extern __shared__ __half smh[];
    const uint32_t smem_u32 = (uint32_t)__cvta_generic_to_shared(smh);

    const int tid  = threadIdx.x;
    const int lane = tid & 31;
    const int warp = tid >> 5;          // 0..7, each 16 q-rows
    const int lg = lane >> 2;
    const int lt = lane & 3;

    const int qb = gridDim.x - 1 - blockIdx.x;   // heavy tiles first
    const int bh = blockIdx.y;                    // b*16 + h
    const int b  = bh >> 4;
    const int h  = bh & 15;
    const int q0 = qb * 128;
    const size_t rowbase = (size_t)b * T_SEQ;

    // ---- stage Q: fp32 -> x0.125 -> fp16 ----
    {
        __half2* qh2 = reinterpret_cast<__half2*>(smh);
        #pragma unroll
        for (int p = 0; p < 8; p++) {
            const int r = p * 16 + (tid >> 4);
            const int cc = (tid & 15) * 4;
            const float4 v = *reinterpret_cast<const float4*>(
                &qkv[(rowbase + q0 + r) * (size_t)(3 * D_MODEL) + h * HDIM + cc]);
            qh2[(r * QH + cc) >> 1]       = __floats2half2_rn(v.x * 0.125f, v.y * 0.125f);
            qh2[((r * QH + cc) >> 1) + 1] = __floats2half2_rn(v.z * 0.125f, v.w * 0.125f);
        }
    }

    // cp.async coords: 64 rows x 64 halves per tile; 2 chunks of 16B per thread
    const int kv_r = tid >> 2;          // 0..63
    const int kv_c = (tid & 3) * 16;    // halves

    const __half* kbase  = k16  + (size_t)bh * T_SEQ * HDIM;
    const __half* vtbase = v16t + (size_t)bh * HDIM * T_SEQ;

    auto prefetch = [&](int kb, int st) {
        const uint32_t kdst  = smem_u32 + (K_OFF  + st * K_HALF  + kv_r * KH  + kv_c) * 2;
        const uint32_t vtdst = smem_u32 + (VT_OFF + st * VT_HALF + kv_r * VTH + kv_c) * 2;
        const __half* ksrc  = kbase  + ((size_t)(kb * 64 + kv_r)) * HDIM + kv_c;
        const __half* vtsrc = vtbase + (size_t)kv_r * T_SEQ + kb * 64 + kv_c;
        cp16(kdst,       ksrc);
        cp16(kdst + 16,  ksrc + 8);
        cp16(vtdst,      vtsrc);
        cp16(vtdst + 16, vtsrc + 8);
        cp_commit();
    };

    float o[8][4];
    #pragma unroll
    for (int i = 0; i < 8; i++)
        #pragma unroll
        for (int j = 0; j < 4; j++) o[i][j] = 0.0f;
    float m0 = -INFINITY, m1 = -INFINITY;
    float l0 = 0.0f, l1 = 0.0f;

    const int nkb = 2 * qb + 2;
    prefetch(0, 0);
    __syncthreads();   // Q staged

    const int qm = warp * 16 + lg;

    for (int kb = 0; kb < nkb; kb++) {
        const int st = kb & 1;
        if (kb + 1 < nkb) { prefetch(kb + 1, st ^ 1); cp_wait1(); }
        else              { cp_wait0(); }
        __syncthreads();

        const __half* Ks  = smh + K_OFF  + st * K_HALF;
        const __half* VTs = smh + VT_OFF + st * VT_HALF;

        // ---- S = Q K^T (fp16 m16n8k16) ----
        float s[8][4];
        #pragma unroll
        for (int i = 0; i < 8; i++)
            #pragma unroll
            for (int j = 0; j < 4; j++) s[i][j] = 0.0f;
        #pragma unroll
        for (int kt = 0; kt < 4; kt++) {
            const int kc = kt * 16 + 2 * lt;   // halves
            const uint32_t a0 = *reinterpret_cast<const uint32_t*>(&smh[qm * QH + kc]);
            const uint32_t a1 = *reinterpret_cast<const uint32_t*>(&smh[(qm + 8) * QH + kc]);
            const uint32_t a2 = *reinterpret_cast<const uint32_t*>(&smh[qm * QH + kc + 8]);
            const uint32_t a3 = *reinterpret_cast<const uint32_t*>(&smh[(qm + 8) * QH + kc + 8]);
            #pragma unroll
            for (int nt = 0; nt < 8; nt++) {
                const int n = nt * 8 + lg;
                const uint32_t b0 = *reinterpret_cast<const uint32_t*>(&Ks[n * KH + kc]);
                const uint32_t b1 = *reinterpret_cast<const uint32_t*>(&Ks[n * KH + kc + 8]);
                mma_f16(s[nt], a0, a1, a2, a3, b0, b1);
            }
        }

        // ---- causal mask (diagonal tiles only) ----
        const int t0 = kb * 64;
        if (t0 + 63 > q0 + warp * 16) {
            #pragma unroll
            for (int nt = 0; nt < 8; nt++) {
                #pragma unroll
                for (int j = 0; j < 4; j++) {
                    const int trow = q0 + warp * 16 + lg + (j >= 2 ? 8 : 0);
                    const int tcol = t0 + nt * 8 + 2 * lt + (j & 1);
                    if (tcol > trow) s[nt][j] = -INFINITY;
                }
            }
        }

        // ---- online softmax ----
        float mx0 = -INFINITY, mx1 = -INFINITY;
        #pragma unroll
        for (int nt = 0; nt < 8; nt++) {
            mx0 = fmaxf(mx0, fmaxf(s[nt][0], s[nt][1]));
            mx1 = fmaxf(mx1, fmaxf(s[nt][2], s[nt][3]));
        }
        mx0 = fmaxf(mx0, __shfl_xor_sync(0xffffffff, mx0, 1));
        mx0 = fmaxf(mx0, __shfl_xor_sync(0xffffffff, mx0, 2));
        mx1 = fmaxf(mx1, __shfl_xor_sync(0xffffffff, mx1, 1));
        mx1 = fmaxf(mx1, __shfl_xor_sync(0xffffffff, mx1, 2));
        const float mn0 = fmaxf(m0, mx0);
        const float mn1 = fmaxf(m1, mx1);

        float sum0 = 0.0f, sum1 = 0.0f;
        #pragma unroll
        for (int nt = 0; nt < 8; nt++) {
            s[nt][0] = __expf(s[nt][0] - mn0);
            s[nt][1] = __expf(s[nt][1] - mn0);
            s[nt][2] = __expf(s[nt][2] - mn1);
            s[nt][3] = __expf(s[nt][3] - mn1);
            sum0 += s[nt][0] + s[nt][1];
            sum1 += s[nt][2] + s[nt][3];
        }
        sum0 += __shfl_xor_sync(0xffffffff, sum0, 1);
        sum0 += __shfl_xor_sync(0xffffffff, sum0, 2);
        sum1 += __shfl_xor_sync(0xffffffff, sum1, 1);
        sum1 += __shfl_xor_sync(0xffffffff, sum1, 2);

        const float a0f = __expf(m0 - mn0);
        const float a1f = __expf(m1 - mn1);
        l0 = l0 * a0f + sum0;
        l1 = l1 * a1f + sum1;
        m0 = mn0; m1 = mn1;
        #pragma unroll
        for (int nt = 0; nt < 8; nt++) {
            o[nt][0] *= a0f; o[nt][1] *= a0f;
            o[nt][2] *= a1f; o[nt][3] *= a1f;
        }

        // ---- O += P @ V : C-layout == fp16 A-layout after pair packing ----
        #pragma unroll
        for (int kt = 0; kt < 4; kt++) {
            const uint32_t a0 = packh2(s[2*kt][0],   s[2*kt][1]);
            const uint32_t a1 = packh2(s[2*kt][2],   s[2*kt][3]);
            const uint32_t a2 = packh2(s[2*kt+1][0], s[2*kt+1][1]);
            const uint32_t a3 = packh2(s[2*kt+1][2], s[2*kt+1][3]);
            const int tc = kt * 16 + 2 * lt;   // t offset in halves
            #pragma unroll
            for (int nt = 0; nt < 8; nt++) {
                const int d = nt * 8 + lg;
                const uint32_t b0 = *reinterpret_cast<const uint32_t*>(&VTs[d * VTH + tc]);
                const uint32_t b1 = *reinterpret_cast<const uint32_t*>(&VTs[d * VTH + tc + 8]);
                mma_f16(o[nt], a0, a1, a2, a3, b0, b1);
            }
        }
        __syncthreads();
    }

    const float inv0 = 1.0f / l0;
    const float inv1 = 1.0f / l1;
    #pragma unroll
    for (int nt = 0; nt < 8; nt++) {
        const int dcol = h * HDIM + nt * 8 + 2 * lt;
        const size_t r0 = rowbase + q0 + warp * 16 + lg;
        float2 w0; w0.x = to_tf32(o[nt][0] * inv0); w0.y = to_tf32(o[nt][1] * inv0);
        float2 w1; w1.x = to_tf32(o[nt][2] * inv1); w1.y = to_tf32(o[nt][3] * inv1);
        *reinterpret_cast<float2*>(&out[r0 * D_MODEL + dcol])       = w0;
        *reinterpret_cast<float2*>(&out[(r0 + 8) * D_MODEL + dcol]) = w1;
    }
}

// ---------------- launch ----------------
extern "C" void kernel_launch(void* const* d_in, const int* in_sizes, int n_in,
                              void* d_out, int out_size) {
    const float* x      = (const float*)d_in[0];
    const float* ln1_g  = (const float*)d_in[1];
    const float* ln1_b  = (const float*)d_in[2];
    const float* qkv_w  = (const float*)d_in[3];
    const float* qkv_b  = (const float*)d_in[4];
    const float* proj_w = (const float*)d_in[5];
    const float* proj_b = (const float*)d_in[6];
    const float* ln2_g  = (const float*)d_in[7];
    const float* ln2_b  = (const float*)d_in[8];
    const float* mlp_w1 = (const float*)d_in[9];
    const float* mlp_b1 = (const float*)d_in[10];
    const float* mlp_w2 = (const float*)d_in[11];
    const float* mlp_b2 = (const float*)d_in[12];
    float* out = (float*)d_out;

    float *h, *qkv, *attn, *x1, *h2, *ff, *w;
    __half *k16, *v16t;
    cudaGetSymbolAddress((void**)&h,    g_h);
    cudaGetSymbolAddress((void**)&qkv,  g_qkv);
    cudaGetSymbolAddress((void**)&attn, g_attn);
    cudaGetSymbolAddress((void**)&x1,   g_x1);
    cudaGetSymbolAddress((void**)&h2,   g_h2);
    cudaGetSymbolAddress((void**)&ff,   g_ff);
    cudaGetSymbolAddress((void**)&w,    g_w);
    cudaGetSymbolAddress((void**)&k16,  g_k16);
    cudaGetSymbolAddress((void**)&v16t, g_v16t);

    cudaFuncSetAttribute(gemm_tf32_kernel<0>, cudaFuncAttributeMaxDynamicSharedMemorySize, GEMM_SMEM);
    cudaFuncSetAttribute(gemm_tf32_kernel<1>, cudaFuncAttributeMaxDynamicSharedMemorySize, GEMM_SMEM);
    cudaFuncSetAttribute(gemm_tf32_kernel<2>, cudaFuncAttributeMaxDynamicSharedMemorySize, GEMM_SMEM);
    cudaFuncSetAttribute(attn_kernel,         cudaFuncAttributeMaxDynamicSharedMemorySize, ATT_SMEM);

    // 0. rna-round weights
    cvt_kernel<<<SZ_QKV  / 4 / 256, 256>>>(qkv_w,  w + W_QKV,  SZ_QKV  / 4);
    cvt_kernel<<<SZ_PROJ / 4 / 256, 256>>>(proj_w, w + W_PROJ, SZ_PROJ / 4);
    cvt_kernel<<<SZ_MLP1 / 4 / 256, 256>>>(mlp_w1, w + W_MLP1, SZ_MLP1 / 4);
    cvt_kernel<<<SZ_MLP2 / 4 / 256, 256>>>(mlp_w2, w + W_MLP2, SZ_MLP2 / 4);

    // 1. LN1
    ln_kernel<<<NROWS, 256>>>(x, ln1_g, ln1_b, h);
    // 2. QKV: Q fp32 + K/V fp16 (V transposed)
    gemm_tf32_kernel<0><<<dim3(3 * D_MODEL / BN, NROWS / BM), 256, GEMM_SMEM>>>(
        h, w + W_QKV, qkv_b, nullptr, qkv, k16, v16t, NROWS, 3 * D_MODEL, D_MODEL);
    // 3. attention (fp16 tensor path)
    attn_kernel<<<dim3(T_SEQ / 128, BATCH * NHEADS), 256, ATT_SMEM>>>(qkv, k16, v16t, attn);
    // 4. x1 = x + attn @ proj_w + proj_b
    gemm_tf32_kernel<2><<<dim3(D_MODEL / BN, NROWS / BM), 256, GEMM_SMEM>>>(
        attn, w + W_PROJ, proj_b, x, x1, nullptr, nullptr, NROWS, D_MODEL, D_MODEL);
    // 5. LN2
    ln_kernel<<<NROWS, 256>>>(x1, ln2_g, ln2_b, h2);
    // 6. ff = gelu(h2 @ mlp_w1 + mlp_b1)
    gemm_tf32_kernel<1><<<dim3(DFF / BN, NROWS / BM), 256, GEMM_SMEM>>>(
        h2, w + W_MLP1, mlp_b1, nullptr, ff, nullptr, nullptr, NROWS, DFF, D_MODEL);
    // 7. out = x1 + ff @ mlp_w2 + mlp_b2
    gemm_tf32_kernel<2><<<dim3(D_MODEL / BN, NROWS / BM), 256, GEMM_SMEM>>>(
        ff, w + W_MLP2, mlp_b2, x1, out, nullptr, nullptr, NROWS, D_MODEL, DFF);
}

// round 6
// speedup vs baseline: 1.5306x; 1.5306x over previous
#include <cuda_runtime.h>
#include <cuda_fp16.h>
#include <stdint.h>
#include <math.h>

#define D_MODEL 1024
#define T_SEQ   2048
#define BATCH   2
#define NROWS   (BATCH * T_SEQ)
#define DFF     4096
#define NHEADS  16
#define HDIM    64

// ---------------- scratch ----------------
__device__ __align__(16) float g_h   [NROWS * D_MODEL];
__device__ __align__(16) float g_qkv [NROWS * 3 * D_MODEL];
__device__ __align__(16) float g_attn[NROWS * D_MODEL];
__device__ __align__(16) float g_x1  [NROWS * D_MODEL];
__device__ __align__(16) float g_h2  [NROWS * D_MODEL];
__device__ __align__(16) float g_ff  [NROWS * DFF];
// fp16 K [bh][t][d], fp16 V^T [bh][d][t]
__device__ __align__(16) __half g_k16 [BATCH * NHEADS * T_SEQ * HDIM];
__device__ __align__(16) __half g_v16t[BATCH * NHEADS * HDIM * T_SEQ];
// rna-tf32 rounded weights
#define SZ_QKV  (D_MODEL * 3 * D_MODEL)
#define SZ_PROJ (D_MODEL * D_MODEL)
#define SZ_MLP1 (D_MODEL * DFF)
#define SZ_MLP2 (DFF * D_MODEL)
#define W_QKV  0
#define W_PROJ (W_QKV + SZ_QKV)
#define W_MLP1 (W_PROJ + SZ_PROJ)
#define W_MLP2 (W_MLP1 + SZ_MLP1)
#define W_TOT  (W_MLP2 + SZ_MLP2)
__device__ __align__(16) float g_w[W_TOT];

// ---------------- helpers ----------------
__device__ __forceinline__ float to_tf32(float f) {
    uint32_t u;
    asm("cvt.rna.tf32.f32 %0, %1;" : "=r"(u) : "f"(f));
    return __uint_as_float(u);
}

__device__ __forceinline__ void mma_tf32(float* d,
                                         float a0, float a1, float a2, float a3,
                                         float b0, float b1) {
    asm volatile(
        "mma.sync.aligned.m16n8k8.row.col.f32.tf32.tf32.f32 "
        "{%0,%1,%2,%3}, {%4,%5,%6,%7}, {%8,%9}, {%0,%1,%2,%3};\n"
        : "+f"(d[0]), "+f"(d[1]), "+f"(d[2]), "+f"(d[3])
        : "r"(__float_as_uint(a0)), "r"(__float_as_uint(a1)),
          "r"(__float_as_uint(a2)), "r"(__float_as_uint(a3)),
          "r"(__float_as_uint(b0)), "r"(__float_as_uint(b1)));
}

__device__ __forceinline__ void mma_f16(float* d,
                                        uint32_t a0, uint32_t a1, uint32_t a2, uint32_t a3,
                                        uint32_t b0, uint32_t b1) {
    asm volatile(
        "mma.sync.aligned.m16n8k16.row.col.f32.f16.f16.f32 "
        "{%0,%1,%2,%3}, {%4,%5,%6,%7}, {%8,%9}, {%0,%1,%2,%3};\n"
        : "+f"(d[0]), "+f"(d[1]), "+f"(d[2]), "+f"(d[3])
        : "r"(a0), "r"(a1), "r"(a2), "r"(a3), "r"(b0), "r"(b1));
}

__device__ __forceinline__ uint32_t packh2(float lo, float hi) {
    __half2 h = __floats2half2_rn(lo, hi);
    return *reinterpret_cast<uint32_t*>(&h);
}

__device__ __forceinline__ void cp16(uint32_t s, const void* g) {
    asm volatile("cp.async.cg.shared.global [%0], [%1], 16;\n" :: "r"(s), "l"(g));
}
__device__ __forceinline__ void cp_commit() { asm volatile("cp.async.commit_group;\n"); }
__device__ __forceinline__ void cp_wait1()  { asm volatile("cp.async.wait_group 1;\n"); }
__device__ __forceinline__ void cp_wait0()  { asm volatile("cp.async.wait_group 0;\n"); }

// ---------------- weight rna-tf32 conversion ----------------
__global__ void cvt_kernel(const float* __restrict__ src, float* __restrict__ dst, int n4) {
    const int i = blockIdx.x * blockDim.x + threadIdx.x;
    if (i < n4) {
        float4 v = reinterpret_cast<const float4*>(src)[i];
        v.x = to_tf32(v.x); v.y = to_tf32(v.y);
        v.z = to_tf32(v.z); v.w = to_tf32(v.w);
        reinterpret_cast<float4*>(dst)[i] = v;
    }
}

// ---------------- pack K/V to fp16 (V transposed via smem tile) ----------------
// grid: (T_SEQ/64, BATCH*NHEADS), block 256
__global__ void __launch_bounds__(256)
pack_kv_kernel(const float* __restrict__ qkv,
               __half* __restrict__ k16, __half* __restrict__ v16t) {
    __shared__ __half vt[64][72];   // [d][t], padded
    const int tb = blockIdx.x;
    const int bh = blockIdx.y;
    const int b = bh >> 4, h = bh & 15;
    const int tid = threadIdx.x;

    const int r  = tid >> 2;          // t within tile (0..63)
    const int c4 = (tid & 3) * 4;     // float4 chunk base (0,4,8,12)
    const size_t srow = ((size_t)b * T_SEQ + tb * 64 + r) * (3 * D_MODEL) + h * HDIM;

    // K: coalesced convert + store [bh][t][d]
    {
        __half2* dst = reinterpret_cast<__half2*>(
            &g_k16[0] + ((size_t)bh * T_SEQ + tb * 64 + r) * HDIM);
        #pragma unroll
        for (int i = 0; i < 4; i++) {
            const float4 v = *reinterpret_cast<const float4*>(&qkv[srow + D_MODEL + (c4 + i) * 4]);
            dst[(c4 + i) * 2]     = __floats2half2_rn(v.x, v.y);
            dst[(c4 + i) * 2 + 1] = __floats2half2_rn(v.z, v.w);
        }
    }
    // V: convert into smem transposed
    #pragma unroll
    for (int i = 0; i < 4; i++) {
        const float4 v = *reinterpret_cast<const float4*>(&qkv[srow + 2 * D_MODEL + (c4 + i) * 4]);
        const int d = (c4 + i) * 4;
        vt[d][r]     = __float2half_rn(v.x);
        vt[d + 1][r] = __float2half_rn(v.y);
        vt[d + 2][r] = __float2half_rn(v.z);
        vt[d + 3][r] = __float2half_rn(v.w);
    }
    __syncthreads();
    // write out [bh][d][t], 16B stores
    const int d  = tid >> 2;
    const int tc = (tid & 3) * 16;
    uint4* dst = reinterpret_cast<uint4*>(
        &v16t[((size_t)bh * HDIM + d) * T_SEQ + tb * 64 + tc]);
    dst[0] = *reinterpret_cast<uint4*>(&vt[d][tc]);
    dst[1] = *reinterpret_cast<uint4*>(&vt[d][tc + 8]);
    (void)k16;
}

// ---------------- layernorm (rna-rounded output) ----------------
__global__ void ln_kernel(const float* __restrict__ x,
                          const float* __restrict__ g,
                          const float* __restrict__ b,
                          float* __restrict__ out) {
    const int row = blockIdx.x;
    const int tid = threadIdx.x;
    const float4 v = reinterpret_cast<const float4*>(x + (size_t)row * D_MODEL)[tid];
    float s  = v.x + v.y + v.z + v.w;
    float sq = v.x*v.x + v.y*v.y + v.z*v.z + v.w*v.w;

    __shared__ float rs[256];
    __shared__ float rq[256];
    rs[tid] = s; rq[tid] = sq;
    __syncthreads();
    #pragma unroll
    for (int st = 128; st > 0; st >>= 1) {
        if (tid < st) { rs[tid] += rs[tid + st]; rq[tid] += rq[tid + st]; }
        __syncthreads();
    }
    const float mean = rs[0] * (1.0f / D_MODEL);
    const float var  = rq[0] * (1.0f / D_MODEL) - mean * mean;
    const float rstd = rsqrtf(var + 1e-5f);

    const float4 gv = reinterpret_cast<const float4*>(g)[tid];
    const float4 bv = reinterpret_cast<const float4*>(b)[tid];
    float4 o;
    o.x = to_tf32((v.x - mean) * rstd * gv.x + bv.x);
    o.y = to_tf32((v.y - mean) * rstd * gv.y + bv.y);
    o.z = to_tf32((v.z - mean) * rstd * gv.z + bv.z);
    o.w = to_tf32((v.w - mean) * rstd * gv.w + bv.w);
    reinterpret_cast<float4*>(out + (size_t)row * D_MODEL)[tid] = o;
}

// ---------------- tf32 GEMM, cp.async double-buffered ----------------
// EPI: 0 = bias, round output; 1 = bias + exact GELU, round; 2 = bias + residual (fp32)
#define BM 128
#define BN 128
#define BK 32
#define AS_STRIDE 36
#define BS_STRIDE 136
#define A_TILE (BM * AS_STRIDE)
#define B_TILE (BK * BS_STRIDE)
#define GEMM_SMEM ((A_TILE + B_TILE) * 2 * 4)

template<int EPI>
__global__ void __launch_bounds__(256, 2)
gemm_tf32_kernel(const float* __restrict__ A, const float* __restrict__ B,
                 const float* __restrict__ bias, const float* __restrict__ res,
                 float* __restrict__ C, int M, int N, int K) {
    extern __shared__ float sm[];
    const uint32_t smem_u32 = (uint32_t)__cvta_generic_to_shared(sm);

    const int tid    = threadIdx.x;
    const int lane   = tid & 31;
    const int warp   = tid >> 5;
    const int warp_m = warp >> 1;
    const int warp_n = warp & 1;
    const int bm = blockIdx.y * BM;
    const int bn = blockIdx.x * BN;
    const int lg = lane >> 2;
    const int lt = lane & 3;

    float c[2][8][4];
    #pragma unroll
    for (int i = 0; i < 2; i++)
        #pragma unroll
        for (int j = 0; j < 8; j++)
            #pragma unroll
            for (int k = 0; k < 4; k++) c[i][j][k] = 0.0f;

    const int a_row = tid >> 3;
    const int a_col = (tid & 7) * 4;
    const int b_row = tid >> 5;
    const int b_col = (tid & 31) * 4;
    const int KT = K / BK;

    auto load_tile = [&](int k0, int st) {
        const uint32_t abase = smem_u32 + st * A_TILE * 4;
        const uint32_t bbase = smem_u32 + (2 * A_TILE + st * B_TILE) * 4;
        #pragma unroll
        for (int i = 0; i < 4; i++) {
            const int row = a_row + i * 32;
            cp16(abase + (row * AS_STRIDE + a_col) * 4,
                 &A[(size_t)(bm + row) * K + k0 + a_col]);
        }
        #pragma unroll
        for (int i = 0; i < 4; i++) {
            const int row = b_row + i * 8;
            cp16(bbase + (row * BS_STRIDE + b_col) * 4,
                 &B[(size_t)(k0 + row) * N + bn + b_col]);
        }
        cp_commit();
    };

    load_tile(0, 0);

    for (int kt = 0; kt < KT; kt++) {
        const int st = kt & 1;
        if (kt + 1 < KT) { load_tile((kt + 1) * BK, st ^ 1); cp_wait1(); }
        else             { cp_wait0(); }
        __syncthreads();

        const float* As = sm + st * A_TILE;
        const float* Bs = sm + 2 * A_TILE + st * B_TILE;

        #pragma unroll
        for (int ks = 0; ks < 4; ks++) {
            float af[2][4];
            #pragma unroll
            for (int mi = 0; mi < 2; mi++) {
                const int m = warp_m * 32 + mi * 16 + lg;
                const int k = ks * 8 + lt;
                af[mi][0] = As[m * AS_STRIDE + k];
                af[mi][1] = As[(m + 8) * AS_STRIDE + k];
                af[mi][2] = As[m * AS_STRIDE + k + 4];
                af[mi][3] = As[(m + 8) * AS_STRIDE + k + 4];
            }
            float bf[8][2];
            #pragma unroll
            for (int nt = 0; nt < 8; nt++) {
                const int n = warp_n * 64 + nt * 8 + lg;
                const int k = ks * 8 + lt;
                bf[nt][0] = Bs[k * BS_STRIDE + n];
                bf[nt][1] = Bs[(k + 4) * BS_STRIDE + n];
            }
            #pragma unroll
            for (int mi = 0; mi < 2; mi++)
                #pragma unroll
                for (int nt = 0; nt < 8; nt++)
                    mma_tf32(c[mi][nt], af[mi][0], af[mi][1], af[mi][2], af[mi][3],
                             bf[nt][0], bf[nt][1]);
        }
        __syncthreads();
    }

    #pragma unroll
    for (int mi = 0; mi < 2; mi++) {
        #pragma unroll
        for (int nt = 0; nt < 8; nt++) {
            const int col = bn + warp_n * 64 + nt * 8 + 2 * lt;
            const float b0 = bias[col], b1 = bias[col + 1];
            #pragma unroll
            for (int half = 0; half < 2; half++) {
                const int row = bm + warp_m * 32 + mi * 16 + lg + half * 8;
                float v0 = c[mi][nt][half * 2 + 0] + b0;
                float v1 = c[mi][nt][half * 2 + 1] + b1;
                if (EPI == 1) {
                    v0 = 0.5f * v0 * (1.0f + erff(v0 * 0.70710678118654752f));
                    v1 = 0.5f * v1 * (1.0f + erff(v1 * 0.70710678118654752f));
                } else if (EPI == 2) {
                    v0 += res[(size_t)row * N + col];
                    v1 += res[(size_t)row * N + col + 1];
                }
                if (EPI == 0 || EPI == 1) { v0 = to_tf32(v0); v1 = to_tf32(v1); }
                float2 o; o.x = v0; o.y = v1;
                *reinterpret_cast<float2*>(&C[(size_t)row * N + col]) = o;
            }
        }
    }
}

// ---------------- causal flash attention: fp16 m16n8k16 ----------------
#define QH  72
#define KH  72
#define VTH 72
#define Q_OFF   0
#define Q_HALF  (128 * QH)
#define K_OFF   Q_HALF
#define K_HALF  (64 * KH)
#define VT_OFF  (K_OFF + 2 * K_HALF)
#define VT_HALF (64 * VTH)
#define ATT_SMEM ((VT_OFF + 2 * VT_HALF) * 2)

__global__ void __launch_bounds__(256, 2)
attn_kernel(const float* __restrict__ qkv, const __half* __restrict__ k16,
            const __half* __restrict__ v16t, float* __restrict__ out) {
    extern __shared__ __half smh[];
    const uint32_t smem_u32 = (uint32_t)__cvta_generic_to_shared(smh);

    const int tid  = threadIdx.x;
    const int lane = tid & 31;
    const int warp = tid >> 5;
    const int lg = lane >> 2;
    const int lt = lane & 3;

    const int qb = gridDim.x - 1 - blockIdx.x;
    const int bh = blockIdx.y;
    const int b  = bh >> 4;
    const int h  = bh & 15;
    const int q0 = qb * 128;
    const size_t rowbase = (size_t)b * T_SEQ;

    // stage Q: fp32 -> x0.125 -> fp16
    {
        __half2* qh2 = reinterpret_cast<__half2*>(smh);
        #pragma unroll
        for (int p = 0; p < 8; p++) {
            const int r = p * 16 + (tid >> 4);
            const int cc = (tid & 15) * 4;
            const float4 v = *reinterpret_cast<const float4*>(
                &qkv[(rowbase + q0 + r) * (size_t)(3 * D_MODEL) + h * HDIM + cc]);
            qh2[(r * QH + cc) >> 1]       = __floats2half2_rn(v.x * 0.125f, v.y * 0.125f);
            qh2[((r * QH + cc) >> 1) + 1] = __floats2half2_rn(v.z * 0.125f, v.w * 0.125f);
        }
    }

    const int kv_r = tid >> 2;
    const int kv_c = (tid & 3) * 16;

    const __half* kbase  = k16  + (size_t)bh * T_SEQ * HDIM;
    const __half* vtbase = v16t + (size_t)bh * HDIM * T_SEQ;

    auto prefetch = [&](int kb, int st) {
        const uint32_t kdst  = smem_u32 + (K_OFF  + st * K_HALF  + kv_r * KH  + kv_c) * 2;
        const uint32_t vtdst = smem_u32 + (VT_OFF + st * VT_HALF + kv_r * VTH + kv_c) * 2;
        const __half* ksrc  = kbase  + ((size_t)(kb * 64 + kv_r)) * HDIM + kv_c;
        const __half* vtsrc = vtbase + (size_t)kv_r * T_SEQ + kb * 64 + kv_c;
        cp16(kdst,       ksrc);
        cp16(kdst + 16,  ksrc + 8);
        cp16(vtdst,      vtsrc);
        cp16(vtdst + 16, vtsrc + 8);
        cp_commit();
    };

    float o[8][4];
    #pragma unroll
    for (int i = 0; i < 8; i++)
        #pragma unroll
        for (int j = 0; j < 4; j++) o[i][j] = 0.0f;
    float m0 = -INFINITY, m1 = -INFINITY;
    float l0 = 0.0f, l1 = 0.0f;

    const int nkb = 2 * qb + 2;
    prefetch(0, 0);
    __syncthreads();

    const int qm = warp * 16 + lg;

    for (int kb = 0; kb < nkb; kb++) {
        const int st = kb & 1;
        if (kb + 1 < nkb) { prefetch(kb + 1, st ^ 1); cp_wait1(); }
        else              { cp_wait0(); }
        __syncthreads();

        const __half* Ks  = smh + K_OFF  + st * K_HALF;
        const __half* VTs = smh + VT_OFF + st * VT_HALF;

        float s[8][4];
        #pragma unroll
        for (int i = 0; i < 8; i++)
            #pragma unroll
            for (int j = 0; j < 4; j++) s[i][j] = 0.0f;
        #pragma unroll
        for (int kt = 0; kt < 4; kt++) {
            const int kc = kt * 16 + 2 * lt;
            const uint32_t a0 = *reinterpret_cast<const uint32_t*>(&smh[qm * QH + kc]);
            const uint32_t a1 = *reinterpret_cast<const uint32_t*>(&smh[(qm + 8) * QH + kc]);
            const uint32_t a2 = *reinterpret_cast<const uint32_t*>(&smh[qm * QH + kc + 8]);
            const uint32_t a3 = *reinterpret_cast<const uint32_t*>(&smh[(qm + 8) * QH + kc + 8]);
            #pragma unroll
            for (int nt = 0; nt < 8; nt++) {
                const int n = nt * 8 + lg;
                const uint32_t b0 = *reinterpret_cast<const uint32_t*>(&Ks[n * KH + kc]);
                const uint32_t b1 = *reinterpret_cast<const uint32_t*>(&Ks[n * KH + kc + 8]);
                mma_f16(s[nt], a0, a1, a2, a3, b0, b1);
            }
        }

        const int t0 = kb * 64;
        if (t0 + 63 > q0 + warp * 16) {
            #pragma unroll
            for (int nt = 0; nt < 8; nt++) {
                #pragma unroll
                for (int j = 0; j < 4; j++) {
                    const int trow = q0 + warp * 16 + lg + (j >= 2 ? 8 : 0);
                    const int tcol = t0 + nt * 8 + 2 * lt + (j & 1);
                    if (tcol > trow) s[nt][j] = -INFINITY;
                }
            }
        }

        float mx0 = -INFINITY, mx1 = -INFINITY;
        #pragma unroll
        for (int nt = 0; nt < 8; nt++) {
            mx0 = fmaxf(mx0, fmaxf(s[nt][0], s[nt][1]));
            mx1 = fmaxf(mx1, fmaxf(s[nt][2], s[nt][3]));
        }
        mx0 = fmaxf(mx0, __shfl_xor_sync(0xffffffff, mx0, 1));
        mx0 = fmaxf(mx0, __shfl_xor_sync(0xffffffff, mx0, 2));
        mx1 = fmaxf(mx1, __shfl_xor_sync(0xffffffff, mx1, 1));
        mx1 = fmaxf(mx1, __shfl_xor_sync(0xffffffff, mx1, 2));
        const float mn0 = fmaxf(m0, mx0);
        const float mn1 = fmaxf(m1, mx1);

        float sum0 = 0.0f, sum1 = 0.0f;
        #pragma unroll
        for (int nt = 0; nt < 8; nt++) {
            s[nt][0] = __expf(s[nt][0] - mn0);
            s[nt][1] = __expf(s[nt][1] - mn0);
            s[nt][2] = __expf(s[nt][2] - mn1);
            s[nt][3] = __expf(s[nt][3] - mn1);
            sum0 += s[nt][0] + s[nt][1];
            sum1 += s[nt][2] + s[nt][3];
        }
        sum0 += __shfl_xor_sync(0xffffffff, sum0, 1);
        sum0 += __shfl_xor_sync(0xffffffff, sum0, 2);
        sum1 += __shfl_xor_sync(0xffffffff, sum1, 1);
        sum1 += __shfl_xor_sync(0xffffffff, sum1, 2);

        const float a0f = __expf(m0 - mn0);
        const float a1f = __expf(m1 - mn1);
        l0 = l0 * a0f + sum0;
        l1 = l1 * a1f + sum1;
        m0 = mn0; m1 = mn1;
        #pragma unroll
        for (int nt = 0; nt < 8; nt++) {
            o[nt][0] *= a0f; o[nt][1] *= a0f;
            o[nt][2] *= a1f; o[nt][3] *= a1f;
        }

        #pragma unroll
        for (int kt = 0; kt < 4; kt++) {
            const uint32_t a0 = packh2(s[2*kt][0],   s[2*kt][1]);
            const uint32_t a1 = packh2(s[2*kt][2],   s[2*kt][3]);
            const uint32_t a2 = packh2(s[2*kt+1][0], s[2*kt+1][1]);
            const uint32_t a3 = packh2(s[2*kt+1][2], s[2*kt+1][3]);
            const int tc = kt * 16 + 2 * lt;
            #pragma unroll
            for (int nt = 0; nt < 8; nt++) {
                const int d = nt * 8 + lg;
                const uint32_t b0 = *reinterpret_cast<const uint32_t*>(&VTs[d * VTH + tc]);
                const uint32_t b1 = *reinterpret_cast<const uint32_t*>(&VTs[d * VTH + tc + 8]);
                mma_f16(o[nt], a0, a1, a2, a3, b0, b1);
            }
        }
        __syncthreads();
    }

    const float inv0 = 1.0f / l0;
    const float inv1 = 1.0f / l1;
    #pragma unroll
    for (int nt = 0; nt < 8; nt++) {
        const int dcol = h * HDIM + nt * 8 + 2 * lt;
        const size_t r0 = rowbase + q0 + warp * 16 + lg;
        float2 w0; w0.x = to_tf32(o[nt][0] * inv0); w0.y = to_tf32(o[nt][1] * inv0);
        float2 w1; w1.x = to_tf32(o[nt][2] * inv1); w1.y = to_tf32(o[nt][3] * inv1);
        *reinterpret_cast<float2*>(&out[r0 * D_MODEL + dcol])       = w0;
        *reinterpret_cast<float2*>(&out[(r0 + 8) * D_MODEL + dcol]) = w1;
    }
}

// ---------------- launch ----------------
extern "C" void kernel_launch(void* const* d_in, const int* in_sizes, int n_in,
                              void* d_out, int out_size) {
    const float* x      = (const float*)d_in[0];
    const float* ln1_g  = (const float*)d_in[1];
    const float* ln1_b  = (const float*)d_in[2];
    const float* qkv_w  = (const float*)d_in[3];
    const float* qkv_b  = (const float*)d_in[4];
    const float* proj_w = (const float*)d_in[5];
    const float* proj_b = (const float*)d_in[6];
    const float* ln2_g  = (const float*)d_in[7];
    const float* ln2_b  = (const float*)d_in[8];
    const float* mlp_w1 = (const float*)d_in[9];
    const float* mlp_b1 = (const float*)d_in[10];
    const float* mlp_w2 = (const float*)d_in[11];
    const float* mlp_b2 = (const float*)d_in[12];
    float* out = (float*)d_out;

    float *h, *qkv, *attn, *x1, *h2, *ff, *w;
    __half *k16, *v16t;
    cudaGetSymbolAddress((void**)&h,    g_h);
    cudaGetSymbolAddress((void**)&qkv,  g_qkv);
    cudaGetSymbolAddress((void**)&attn, g_attn);
    cudaGetSymbolAddress((void**)&x1,   g_x1);
    cudaGetSymbolAddress((void**)&h2,   g_h2);
    cudaGetSymbolAddress((void**)&ff,   g_ff);
    cudaGetSymbolAddress((void**)&w,    g_w);
    cudaGetSymbolAddress((void**)&k16,  g_k16);
    cudaGetSymbolAddress((void**)&v16t, g_v16t);

    cudaFuncSetAttribute(gemm_tf32_kernel<0>, cudaFuncAttributeMaxDynamicSharedMemorySize, GEMM_SMEM);
    cudaFuncSetAttribute(gemm_tf32_kernel<1>, cudaFuncAttributeMaxDynamicSharedMemorySize, GEMM_SMEM);
    cudaFuncSetAttribute(gemm_tf32_kernel<2>, cudaFuncAttributeMaxDynamicSharedMemorySize, GEMM_SMEM);
    cudaFuncSetAttribute(attn_kernel,         cudaFuncAttributeMaxDynamicSharedMemorySize, ATT_SMEM);

    // 0. rna-round weights
    cvt_kernel<<<SZ_QKV  / 4 / 256, 256>>>(qkv_w,  w + W_QKV,  SZ_QKV  / 4);
    cvt_kernel<<<SZ_PROJ / 4 / 256, 256>>>(proj_w, w + W_PROJ, SZ_PROJ / 4);
    cvt_kernel<<<SZ_MLP1 / 4 / 256, 256>>>(mlp_w1, w + W_MLP1, SZ_MLP1 / 4);
    cvt_kernel<<<SZ_MLP2 / 4 / 256, 256>>>(mlp_w2, w + W_MLP2, SZ_MLP2 / 4);

    // 1. LN1
    ln_kernel<<<NROWS, 256>>>(x, ln1_g, ln1_b, h);
    // 2. QKV (plain fp32 rounded output)
    gemm_tf32_kernel<0><<<dim3(3 * D_MODEL / BN, NROWS / BM), 256, GEMM_SMEM>>>(
        h, w + W_QKV, qkv_b, nullptr, qkv, NROWS, 3 * D_MODEL, D_MODEL);
    // 2b. pack K/V to fp16 (coalesced, smem-tiled V transpose)
    pack_kv_kernel<<<dim3(T_SEQ / 64, BATCH * NHEADS), 256>>>(qkv, k16, v16t);
    // 3. attention (fp16 tensor path)
    attn_kernel<<<dim3(T_SEQ / 128, BATCH * NHEADS), 256, ATT_SMEM>>>(qkv, k16, v16t, attn);
    // 4. x1 = x + attn @ proj_w + proj_b
    gemm_tf32_kernel<2><<<dim3(D_MODEL / BN, NROWS / BM), 256, GEMM_SMEM>>>(
        attn, w + W_PROJ, proj_b, x, x1, NROWS, D_MODEL, D_MODEL);
    // 5. LN2
    ln_kernel<<<NROWS, 256>>>(x1, ln2_g, ln2_b, h2);
    // 6. ff = gelu(h2 @ mlp_w1 + mlp_b1)
    gemm_tf32_kernel<1><<<dim3(DFF / BN, NROWS / BM), 256, GEMM_SMEM>>>(
        h2, w + W_MLP1, mlp_b1, nullptr, ff, NROWS, DFF, D_MODEL);
    // 7. out = x1 + ff @ mlp_w2 + mlp_b2
    gemm_tf32_kernel<2><<<dim3(D_MODEL / BN, NROWS / BM), 256, GEMM_SMEM>>>(
        ff, w + W_MLP2, mlp_b2, x1, out, NROWS, D_MODEL, DFF);
}